// round 9
// baseline (speedup 1.0000x reference)
#include <cuda_runtime.h>
#include <cuda_bf16.h>

// CoverageLoss, fused single-kernel, edge-separable closed form.
//
// Boundary samples are 4 axis-aligned uniform segments of the box; min over an
// edge separates into (perp dist)^2 + min_j (parallel dist)^2; the grid argmin
// is clamp(round(t*99)) with a +/-1 candidate window evaluated against the
// exact lins[] values read from the boundary input (bit-exact vs reference).
//
// R9 layout: 32 blocks x 256 threads; thread = (box, 16 points). Tail uses
// per-block partial slots (plain STG) + a single 32-deep counter atomic;
// last block does a warp-parallel sum of partials, writes out, resets counter.

#define NPTS  2048
#define NBOX  64
#define PPTH  16                      // points per thread
#define NBLK  (NPTS / (PPTH * 4))     // 32 blocks, 64 points per block
#define NLIN  100

__device__ float        g_part[NBLK];
__device__ unsigned int g_cnt = 0u;   // reset by last block each run

__global__ __launch_bounds__(256)
void cl_fused_kernel(const float* __restrict__ pred,
                     const float* __restrict__ frag,
                     const float* __restrict__ boundary,
                     float* __restrict__ out) {
    __shared__ float s_lins[NLIN];
    __shared__ float s_red[8][PPTH];
    __shared__ float s_sum[2];

    const int tid = threadIdx.x;
    if (tid < NLIN) s_lins[tid] = boundary[2 * tid + 1];  // a-part y coords = lins
    __syncthreads();

    const int b  = tid & 63;          // box index
    const int pl = tid >> 6;          // point-slot 0..3 (two warps per slot)

    // ---- box constants (hoisted across 16 points, incl. both MUFU rcp) ----
    const float4 pr = ((const float4*)pred)[b];
    const float lx = pr.x, ly = pr.y, hx = pr.z, hy = pr.w;
    const float wx = hx - lx;
    const float wy = hy - ly;
    const float ex = wx + lx;          // right-edge x as the reference computes it
    const float ey = wy + ly;          // top-edge y
    const float rwx = __frcp_rn(wx);
    const float rwy = __frcp_rn(wy);

    // ---- 16 fragment points: 8x float4 broadcast loads ----
    const int pbase = blockIdx.x * (PPTH * 4) + pl * PPTH;
    float fxs[PPTH], fys[PPTH];
#pragma unroll
    for (int q = 0; q < PPTH / 2; q++) {
        float4 f = ((const float4*)frag)[pbase / 2 + q];
        fxs[2 * q]     = f.x;  fys[2 * q]     = f.y;
        fxs[2 * q + 1] = f.z;  fys[2 * q + 1] = f.w;
    }

    float vals[PPTH];
#pragma unroll
    for (int i = 0; i < PPTH; i++) {
        const float fx = fxs[i], fy = fys[i];
        const bool inside = (fx >= lx) && (fy >= ly) && (hx >= fx) && (hy >= fy);

        // vertical edges: x fixed, min over y samples
        const float dyl = fy - ly;
        float jf = fminf(fmaxf(rintf(dyl * 99.0f * rwy), 0.0f), 99.0f);  // NaN->0
        int   j  = (int)jf;
        int   j0 = max(j - 1, 0), j2 = min(j + 1, NLIN - 1);
        float d, mdy2;
        d = fy - (s_lins[j ] * wy + ly); mdy2 = d * d;
        d = fy - (s_lins[j0] * wy + ly); mdy2 = fminf(mdy2, d * d);
        d = fy - (s_lins[j2] * wy + ly); mdy2 = fminf(mdy2, d * d);
        const float dxl = fx - lx;
        const float dxh = fx - ex;
        const float dvert = fminf(dxl * dxl, dxh * dxh) + mdy2;

        // horizontal edges: y fixed, min over x samples
        float kf = fminf(fmaxf(rintf(dxl * 99.0f * rwx), 0.0f), 99.0f);
        int   k  = (int)kf;
        int   k0 = max(k - 1, 0), k2 = min(k + 1, NLIN - 1);
        float mdx2;
        d = fx - (s_lins[k ] * wx + lx); mdx2 = d * d;
        d = fx - (s_lins[k0] * wx + lx); mdx2 = fminf(mdx2, d * d);
        d = fx - (s_lins[k2] * wx + lx); mdx2 = fminf(mdx2, d * d);
        const float dyh = fy - ey;
        const float dhorz = fminf(dyl * dyl, dyh * dyh) + mdx2;

        vals[i] = inside ? 0.0f : fminf(dvert, dhorz);
    }

    // ---- min over 64 boxes: shuffle within warp (32 boxes), pair via shared ----
#pragma unroll
    for (int o = 16; o > 0; o >>= 1) {
#pragma unroll
        for (int i = 0; i < PPTH; i++)
            vals[i] = fminf(vals[i], __shfl_xor_sync(0xffffffffu, vals[i], o));
    }
    if ((tid & 31) == 0) {
        const int w = tid >> 5;
#pragma unroll
        for (int i = 0; i < PPTH; i++) s_red[w][i] = vals[i];
    }
    __syncthreads();

    // ---- block partial: 64 threads pair-min + add-reduce ----
    if (tid < 64) {
        const int slot = tid >> 4;     // 0..3
        const int i    = tid & 15;     // 0..15
        float v = fminf(s_red[2 * slot][i], s_red[2 * slot + 1][i]);
#pragma unroll
        for (int o = 16; o > 0; o >>= 1)
            v += __shfl_xor_sync(0xffffffffu, v, o);
        if ((tid & 31) == 0) s_sum[tid >> 5] = v;
    }
    __syncthreads();

    // ---- tail: distinct-slot partial store + 32-deep counter; warp-parallel finale ----
    if (tid < 32) {
        unsigned done = 0;
        if (tid == 0) {
            g_part[blockIdx.x] = s_sum[0] + s_sum[1];
            __threadfence();
            done = atomicAdd(&g_cnt, 1u);
        }
        done = __shfl_sync(0xffffffffu, done, 0);
        if (done == NBLK - 1) {                 // last block: all partials visible
            __threadfence();
            float v = g_part[tid];              // one partial per lane (NBLK == 32)
#pragma unroll
            for (int o = 16; o > 0; o >>= 1)
                v += __shfl_xor_sync(0xffffffffu, v, o);
            if (tid == 0) {
                out[0] = v * (1.0f / 64.0f);    // / FP
                g_cnt = 0u;                     // restore invariant for next replay
            }
        }
    }
}

extern "C" void kernel_launch(void* const* d_in, const int* in_sizes, int n_in,
                              void* d_out, int out_size) {
    const float* pred     = (const float*)d_in[0];   // [64,4]
    const float* frag     = (const float*)d_in[1];   // [32,64,2]
    const float* boundary = (const float*)d_in[2];   // [1,400,2]
    cl_fused_kernel<<<NBLK, 256>>>(pred, frag, boundary, (float*)d_out);
}

// round 10
// speedup vs baseline: 1.2132x; 1.2132x over previous
#include <cuda_runtime.h>
#include <cuda_bf16.h>

// CoverageLoss, fused single-kernel, edge-separable closed form.
//
// Boundary samples are 4 axis-aligned uniform segments of the box; min over an
// edge separates into (perp dist)^2 + min_j (parallel dist)^2; the grid argmin
// is clamp(round(t*99)) with a +/-1 candidate window evaluated against the
// exact lins[] values read from the boundary input (matches reference samples).
//
// R10: R8 compute layout (128 blocks x 256 threads, thread = (box, 4 points),
// proven 6.0us kernel) with a restructured tail: distinct-slot STG partials +
// one counter atomic per block, warp-parallel last-block finale.

#define NPTS  2048
#define NBOX  64
#define PPTH  4                       // points per thread
#define NBLK  (NPTS / (PPTH * 4))     // 128 blocks, 16 points per block
#define NLIN  100

__device__ float        g_part[NBLK];
__device__ unsigned int g_cnt = 0u;   // reset by last block each run

__global__ __launch_bounds__(256)
void cl_fused_kernel(const float* __restrict__ pred,
                     const float* __restrict__ frag,
                     const float* __restrict__ boundary,
                     float* __restrict__ out) {
    __shared__ float s_lins[NLIN];
    __shared__ float s_red[8][PPTH];

    const int tid = threadIdx.x;
    if (tid < NLIN) s_lins[tid] = boundary[2 * tid + 1];  // a-part y coords = lins
    __syncthreads();

    const int b  = tid & 63;          // box index
    const int pl = tid >> 6;          // point-slot 0..3 (two warps per slot)

    // ---- box constants (hoisted across 4 points, incl. both MUFU rcp) ----
    const float4 pr = ((const float4*)pred)[b];
    const float lx = pr.x, ly = pr.y, hx = pr.z, hy = pr.w;
    const float wx = hx - lx;
    const float wy = hy - ly;
    const float ex = wx + lx;          // right-edge x as the reference computes it
    const float ey = wy + ly;          // top-edge y
    const float rwx = __frcp_rn(wx);
    const float rwy = __frcp_rn(wy);

    // ---- 4 fragment points, contiguous: 2x float4 loads ----
    const int pbase = blockIdx.x * 16 + pl * PPTH;
    const float4 f01 = ((const float4*)frag)[pbase / 2];
    const float4 f23 = ((const float4*)frag)[pbase / 2 + 1];
    float fxs[PPTH] = {f01.x, f01.z, f23.x, f23.z};
    float fys[PPTH] = {f01.y, f01.w, f23.y, f23.w};

    float vals[PPTH];
#pragma unroll
    for (int i = 0; i < PPTH; i++) {
        const float fx = fxs[i], fy = fys[i];
        const bool inside = (fx >= lx) && (fy >= ly) && (hx >= fx) && (hy >= fy);

        // vertical edges: x fixed, min over y samples
        const float dyl = fy - ly;
        float jf = fminf(fmaxf(rintf(dyl * 99.0f * rwy), 0.0f), 99.0f);  // NaN->0
        int   j  = (int)jf;
        int   j0 = max(j - 1, 0), j2 = min(j + 1, NLIN - 1);
        float d, mdy2;
        d = fy - (s_lins[j ] * wy + ly); mdy2 = d * d;
        d = fy - (s_lins[j0] * wy + ly); mdy2 = fminf(mdy2, d * d);
        d = fy - (s_lins[j2] * wy + ly); mdy2 = fminf(mdy2, d * d);
        const float dxl = fx - lx;
        const float dxh = fx - ex;
        const float dvert = fminf(dxl * dxl, dxh * dxh) + mdy2;

        // horizontal edges: y fixed, min over x samples
        float kf = fminf(fmaxf(rintf(dxl * 99.0f * rwx), 0.0f), 99.0f);
        int   k  = (int)kf;
        int   k0 = max(k - 1, 0), k2 = min(k + 1, NLIN - 1);
        float mdx2;
        d = fx - (s_lins[k ] * wx + lx); mdx2 = d * d;
        d = fx - (s_lins[k0] * wx + lx); mdx2 = fminf(mdx2, d * d);
        d = fx - (s_lins[k2] * wx + lx); mdx2 = fminf(mdx2, d * d);
        const float dyh = fy - ey;
        const float dhorz = fminf(dyl * dyl, dyh * dyh) + mdx2;

        vals[i] = inside ? 0.0f : fminf(dvert, dhorz);
    }

    // ---- min over 64 boxes: shuffle within warp (32 boxes), pair via shared ----
#pragma unroll
    for (int o = 16; o > 0; o >>= 1) {
#pragma unroll
        for (int i = 0; i < PPTH; i++)
            vals[i] = fminf(vals[i], __shfl_xor_sync(0xffffffffu, vals[i], o));
    }
    if ((tid & 31) == 0) {
        const int w = tid >> 5;
#pragma unroll
        for (int i = 0; i < PPTH; i++) s_red[w][i] = vals[i];
    }
    __syncthreads();

    // ---- tail: 16-lane pair-min + sum, slot STG + counter; warp-parallel finale ----
    if (tid < 32) {
        float v = 0.0f;
        if (tid < 16) {
            const int slot = tid >> 2;     // 0..3 point-slot
            const int i    = tid & 3;      // 0..3 point-in-slot
            v = fminf(s_red[2 * slot][i], s_red[2 * slot + 1][i]);
        }
#pragma unroll
        for (int o = 8; o > 0; o >>= 1)
            v += __shfl_xor_sync(0xffffffffu, v, o);

        unsigned done = 0;
        if (tid == 0) {
            g_part[blockIdx.x] = v;        // distinct slot: no same-address contention
            __threadfence();
            done = atomicAdd(&g_cnt, 1u);
        }
        done = __shfl_sync(0xffffffffu, done, 0);
        if (done == NBLK - 1) {            // last block: all partials visible
            __threadfence();
            const float4 p = ((const float4*)g_part)[tid];  // 4 partials per lane
            float s = (p.x + p.y) + (p.z + p.w);
#pragma unroll
            for (int o = 16; o > 0; o >>= 1)
                s += __shfl_xor_sync(0xffffffffu, s, o);
            if (tid == 0) {
                out[0] = s * (1.0f / 64.0f);   // / FP
                g_cnt = 0u;                    // restore invariant for next replay
            }
        }
    }
}

extern "C" void kernel_launch(void* const* d_in, const int* in_sizes, int n_in,
                              void* d_out, int out_size) {
    const float* pred     = (const float*)d_in[0];   // [64,4]
    const float* frag     = (const float*)d_in[1];   // [32,64,2]
    const float* boundary = (const float*)d_in[2];   // [1,400,2]
    cl_fused_kernel<<<NBLK, 256>>>(pred, frag, boundary, (float*)d_out);
}

// round 11
// speedup vs baseline: 1.5349x; 1.2651x over previous
#include <cuda_runtime.h>
#include <cuda_bf16.h>

// CoverageLoss, fused single-kernel, edge-separable closed form.
//
// Boundary samples are 4 axis-aligned uniform segments of the box; min over an
// edge separates into (perp dist)^2 + min_j (parallel dist)^2; the grid argmin
// is clamp(round(t*99)), evaluated against the exact lins[] value read from
// the boundary input. (Nearest-candidate only: a wrong rounding pick happens
// only at sample midpoints where the two squared distances agree to ~ulp.)
//
// Layout (R8, empirically fastest): 128 blocks x 256 threads; thread =
// (box, 4 points). Box constants incl. both MUFU rcp hoisted; 4-way ILP.
// Tail: one contended atomicAdd(g_sum) per block (pipelines well), counter,
// last block writes out and resets scratch (graph-replay safe).

#define NPTS  2048
#define NBOX  64
#define PPTH  4                       // points per thread
#define NBLK  (NPTS / (PPTH * 4))     // 128 blocks, 16 points per block
#define NLIN  100

__device__ float        g_sum = 0.0f;   // static zero-init; reset by last block
__device__ unsigned int g_cnt = 0u;

__global__ __launch_bounds__(256)
void cl_fused_kernel(const float* __restrict__ pred,
                     const float* __restrict__ frag,
                     const float* __restrict__ boundary,
                     float* __restrict__ out) {
    __shared__ float s_lins[NLIN];
    __shared__ float s_red[8][PPTH];

    const int tid = threadIdx.x;
    // a-part of boundary: rows (2*t, 2*t+1) -> y coords are lins[2t], lins[2t+1]
    if (tid < NLIN / 2) {
        float4 bb = ((const float4*)boundary)[tid];
        s_lins[2 * tid]     = bb.y;
        s_lins[2 * tid + 1] = bb.w;
    }
    __syncthreads();

    const int b  = tid & 63;          // box index
    const int pl = tid >> 6;          // point-slot 0..3 (two warps per slot)

    // ---- box constants (hoisted across 4 points, incl. both MUFU rcp) ----
    const float4 pr = ((const float4*)pred)[b];
    const float lx = pr.x, ly = pr.y, hx = pr.z, hy = pr.w;
    const float wx = hx - lx;
    const float wy = hy - ly;
    const float ex = wx + lx;          // right-edge x as the reference computes it
    const float ey = wy + ly;          // top-edge y
    const float rwx = __frcp_rn(wx);
    const float rwy = __frcp_rn(wy);

    // ---- 4 fragment points, contiguous: 2x float4 loads ----
    const int pbase = blockIdx.x * 16 + pl * PPTH;
    const float4 f01 = ((const float4*)frag)[pbase / 2];
    const float4 f23 = ((const float4*)frag)[pbase / 2 + 1];
    float fxs[PPTH] = {f01.x, f01.z, f23.x, f23.z};
    float fys[PPTH] = {f01.y, f01.w, f23.y, f23.w};

    float vals[PPTH];
#pragma unroll
    for (int i = 0; i < PPTH; i++) {
        const float fx = fxs[i], fy = fys[i];
        const bool inside = (fx >= lx) && (fy >= ly) && (hx >= fx) && (hy >= fy);

        // vertical edges: x fixed, nearest y sample (F2I of NaN -> 0, clamp safe)
        const float dyl = fy - ly;
        const int j = min(max(__float2int_rn(dyl * 99.0f * rwy), 0), NLIN - 1);
        float d = fy - fmaf(s_lins[j], wy, ly);
        const float mdy2 = d * d;
        const float dxl = fx - lx;
        const float dxh = fx - ex;
        const float dvert = fminf(dxl * dxl, dxh * dxh) + mdy2;

        // horizontal edges: y fixed, nearest x sample
        const int k = min(max(__float2int_rn(dxl * 99.0f * rwx), 0), NLIN - 1);
        d = fx - fmaf(s_lins[k], wx, lx);
        const float mdx2 = d * d;
        const float dyh = fy - ey;
        const float dhorz = fminf(dyl * dyl, dyh * dyh) + mdx2;

        vals[i] = inside ? 0.0f : fminf(dvert, dhorz);
    }

    // ---- min over 64 boxes: shuffle within warp (32 boxes), pair via shared ----
#pragma unroll
    for (int o = 16; o > 0; o >>= 1) {
#pragma unroll
        for (int i = 0; i < PPTH; i++)
            vals[i] = fminf(vals[i], __shfl_xor_sync(0xffffffffu, vals[i], o));
    }
    if ((tid & 31) == 0) {
        const int w = tid >> 5;
#pragma unroll
        for (int i = 0; i < PPTH; i++) s_red[w][i] = vals[i];
    }
    __syncthreads();

    // ---- tail (R8 verbatim): contended atomicAdd + counter, serial finale ----
    if (tid == 0) {
        float s = 0.0f;
#pragma unroll
        for (int p = 0; p < 4; p++)
#pragma unroll
            for (int i = 0; i < PPTH; i++)
                s += fminf(s_red[2 * p][i], s_red[2 * p + 1][i]);
        atomicAdd(&g_sum, s);
        __threadfence();
        unsigned done = atomicAdd(&g_cnt, 1u);
        if (done == NBLK - 1) {
            float tot = atomicAdd(&g_sum, 0.0f);   // atomic read-back
            out[0] = tot * (1.0f / 64.0f);         // / FP
            g_sum = 0.0f;                          // restore invariant for replay
            g_cnt = 0u;
        }
    }
}

extern "C" void kernel_launch(void* const* d_in, const int* in_sizes, int n_in,
                              void* d_out, int out_size) {
    const float* pred     = (const float*)d_in[0];   // [64,4]
    const float* frag     = (const float*)d_in[1];   // [32,64,2]
    const float* boundary = (const float*)d_in[2];   // [1,400,2]
    cl_fused_kernel<<<NBLK, 256>>>(pred, frag, boundary, (float*)d_out);
}